// round 1
// baseline (speedup 1.0000x reference)
#include <cuda_runtime.h>
#include <cstdint>

// Problem constants (B=32, N=1024 -> 32768 rows; F=512; H=2048)
#define ROWS 32768
#define FDIM 512
#define HDIM 2048

// Scratch (device globals: allocation-free per harness rules)
__device__ float          g_xs[(size_t)ROWS * FDIM];     // permuted input, fp32
__device__ unsigned short g_inv[(size_t)ROWS * FDIM];    // inverse permutation per row
__device__ float          g_h [(size_t)ROWS * HDIM];     // hidden activations

// ---------------------------------------------------------------------------
// Kernel 1: per-row stable argsort (bitonic on 64-bit keys) + produce xs, inv
//   key = ordered(float) << 32 | index  -> stable ascending sort
//   xs[j] = x[inv[j]]  (coalesced write, gather from shared)
// ---------------------------------------------------------------------------
__global__ void sort_scatter_kernel(const float* __restrict__ x) {
    __shared__ unsigned long long keys[FDIM];
    __shared__ float              xsh[FDIM];
    __shared__ unsigned short     invsh[FDIM];

    const int row = blockIdx.x;
    const int tid = threadIdx.x;           // 256 threads
    const float* xr = x + (size_t)row * FDIM;

#pragma unroll
    for (int t = 0; t < 2; t++) {
        int i = tid + t * 256;
        float v = xr[i];
        xsh[i] = v;
        unsigned u = __float_as_uint(v);
        u = (u & 0x80000000u) ? ~u : (u | 0x80000000u);   // order-preserving map
        keys[i] = ((unsigned long long)u << 32) | (unsigned)i;
    }
    __syncthreads();

    for (int k = 2; k <= FDIM; k <<= 1) {
        for (int j = k >> 1; j > 0; j >>= 1) {
#pragma unroll
            for (int t = 0; t < 2; t++) {
                int i = tid + t * 256;
                int p = i ^ j;
                if (p > i) {
                    unsigned long long a = keys[i];
                    unsigned long long b = keys[p];
                    bool up = ((i & k) == 0);
                    bool sw = up ? (a > b) : (a < b);
                    if (sw) { keys[i] = b; keys[p] = a; }
                }
            }
            __syncthreads();
        }
    }

    // keys[pos] sorted ascending; srt[pos] = low bits; inv[srt[pos]] = pos
#pragma unroll
    for (int t = 0; t < 2; t++) {
        int pos = tid + t * 256;
        unsigned srt = (unsigned)(keys[pos] & 0xFFFFFFFFu);
        invsh[srt] = (unsigned short)pos;
    }
    __syncthreads();

#pragma unroll
    for (int t = 0; t < 2; t++) {
        int i = tid + t * 256;
        unsigned short iv = invsh[i];
        g_inv[(size_t)row * FDIM + i] = iv;
        g_xs [(size_t)row * FDIM + i] = xsh[iv];   // xs[i] = x[inv[i]]
    }
}

// ---------------------------------------------------------------------------
// TF32 tensor-core GEMM building blocks (mma.sync m16n8k8, fp32 accum)
// CTA tile 128x128, K-step 32, 8 warps in 2(M) x 4(N), warp tile 64x32
// ---------------------------------------------------------------------------
__device__ __forceinline__ unsigned cvt_tf32(float f) {
    unsigned u;
    asm("cvt.rna.tf32.f32 %0, %1;" : "=r"(u) : "f"(f));
    return u;
}

__device__ __forceinline__ void mma_tf32(float (&c)[4], const unsigned (&a)[4],
                                         const unsigned (&b)[2]) {
    asm volatile(
        "mma.sync.aligned.m16n8k8.row.col.f32.tf32.tf32.f32 "
        "{%0,%1,%2,%3}, {%4,%5,%6,%7}, {%8,%9}, {%0,%1,%2,%3};"
        : "+f"(c[0]), "+f"(c[1]), "+f"(c[2]), "+f"(c[3])
        : "r"(a[0]), "r"(a[1]), "r"(a[2]), "r"(a[3]), "r"(b[0]), "r"(b[1]));
}

// A: [M, KDIM] row-major, B: [N, KDIM] row-major (i.e. "col-major" KxN for mma)
template <int KDIM>
__device__ __forceinline__ void gemm_tile_compute(
    const float* __restrict__ A, const float* __restrict__ B,
    float (&acc)[4][4][4], float (*As)[36], float (*Bs)[36]) {

    const int tid    = threadIdx.x;
    const int lane   = tid & 31;
    const int warp   = tid >> 5;
    const int warp_m = warp >> 2;   // 0..1
    const int warp_n = warp & 3;    // 0..3
    const int ldr    = tid >> 3;          // staging row 0..31
    const int ldc    = (tid & 7) * 4;     // staging col 0,4,...,28
    const int blockM = blockIdx.y * 128;
    const int blockN = blockIdx.x * 128;

    for (int kt = 0; kt < KDIM; kt += 32) {
#pragma unroll
        for (int rr = 0; rr < 4; rr++) {
            int r = ldr + rr * 32;
            float4 va = *reinterpret_cast<const float4*>(
                &A[(size_t)(blockM + r) * KDIM + kt + ldc]);
            *reinterpret_cast<float4*>(&As[r][ldc]) = va;
            float4 vb = *reinterpret_cast<const float4*>(
                &B[(size_t)(blockN + r) * KDIM + kt + ldc]);
            *reinterpret_cast<float4*>(&Bs[r][ldc]) = vb;
        }
        __syncthreads();

#pragma unroll
        for (int kk = 0; kk < 32; kk += 8) {
            unsigned a[4][4], b[4][2];
#pragma unroll
            for (int mf = 0; mf < 4; mf++) {
                int ar = warp_m * 64 + mf * 16 + (lane >> 2);
                int ac = kk + (lane & 3);
                a[mf][0] = cvt_tf32(As[ar][ac]);
                a[mf][1] = cvt_tf32(As[ar + 8][ac]);
                a[mf][2] = cvt_tf32(As[ar][ac + 4]);
                a[mf][3] = cvt_tf32(As[ar + 8][ac + 4]);
            }
#pragma unroll
            for (int nf = 0; nf < 4; nf++) {
                int br = warp_n * 32 + nf * 8 + (lane >> 2);
                int bc = kk + (lane & 3);
                b[nf][0] = cvt_tf32(Bs[br][bc]);
                b[nf][1] = cvt_tf32(Bs[br][bc + 4]);
            }
#pragma unroll
            for (int mf = 0; mf < 4; mf++)
#pragma unroll
                for (int nf = 0; nf < 4; nf++)
                    mma_tf32(acc[mf][nf], a[mf], b[nf]);
        }
        __syncthreads();
    }
}

// ---------------------------------------------------------------------------
// GEMM1: h = relu(xs @ W1^T + b1),   W1: [HDIM, FDIM] row-major
// ---------------------------------------------------------------------------
__global__ __launch_bounds__(256, 2)
void gemm1_kernel(const float* __restrict__ W1, const float* __restrict__ b1) {
    __shared__ float As[128][36];
    __shared__ float Bs[128][36];
    float acc[4][4][4] = {};

    gemm_tile_compute<FDIM>(g_xs, W1, acc, As, Bs);

    const int tid    = threadIdx.x;
    const int lane   = tid & 31;
    const int warp   = tid >> 5;
    const int warp_m = warp >> 2;
    const int warp_n = warp & 3;
    const int blockM = blockIdx.y * 128;
    const int blockN = blockIdx.x * 128;

#pragma unroll
    for (int mf = 0; mf < 4; mf++) {
#pragma unroll
        for (int nf = 0; nf < 4; nf++) {
            int row = blockM + warp_m * 64 + mf * 16 + (lane >> 2);
            int col = blockN + warp_n * 32 + nf * 8 + (lane & 3) * 2;
            float bb0 = b1[col], bb1 = b1[col + 1];
            float2 v0, v1;
            v0.x = fmaxf(acc[mf][nf][0] + bb0, 0.f);
            v0.y = fmaxf(acc[mf][nf][1] + bb1, 0.f);
            v1.x = fmaxf(acc[mf][nf][2] + bb0, 0.f);
            v1.y = fmaxf(acc[mf][nf][3] + bb1, 0.f);
            *reinterpret_cast<float2*>(&g_h[(size_t)row * HDIM + col])       = v0;
            *reinterpret_cast<float2*>(&g_h[(size_t)(row + 8) * HDIM + col]) = v1;
        }
    }
}

// ---------------------------------------------------------------------------
// GEMM2: y = h @ W2^T + b2 + xs, then scatter out[m][inv[n]] = y[m][n]
//   W2: [FDIM, HDIM] row-major
// ---------------------------------------------------------------------------
__global__ __launch_bounds__(256, 2)
void gemm2_kernel(const float* __restrict__ W2, const float* __restrict__ b2,
                  float* __restrict__ out) {
    __shared__ float As[128][36];
    __shared__ float Bs[128][36];
    float acc[4][4][4] = {};

    gemm_tile_compute<HDIM>(g_h, W2, acc, As, Bs);

    const int tid    = threadIdx.x;
    const int lane   = tid & 31;
    const int warp   = tid >> 5;
    const int warp_m = warp >> 2;
    const int warp_n = warp & 3;
    const int blockM = blockIdx.y * 128;
    const int blockN = blockIdx.x * 128;

#pragma unroll
    for (int mf = 0; mf < 4; mf++) {
#pragma unroll
        for (int nf = 0; nf < 4; nf++) {
            int row = blockM + warp_m * 64 + mf * 16 + (lane >> 2);
            int col = blockN + warp_n * 32 + nf * 8 + (lane & 3) * 2;
            float bb0 = b2[col], bb1 = b2[col + 1];
#pragma unroll
            for (int half = 0; half < 2; half++) {
                int r = row + half * 8;
                size_t base = (size_t)r * FDIM + col;
                float y0 = acc[mf][nf][half * 2 + 0] + bb0 + g_xs[base];
                float y1 = acc[mf][nf][half * 2 + 1] + bb1 + g_xs[base + 1];
                unsigned short p0 = g_inv[base];
                unsigned short p1 = g_inv[base + 1];
                out[(size_t)r * FDIM + p0] = y0;
                out[(size_t)r * FDIM + p1] = y1;
            }
        }
    }
}

// ---------------------------------------------------------------------------
// Launch
// ---------------------------------------------------------------------------
extern "C" void kernel_launch(void* const* d_in, const int* in_sizes, int n_in,
                              void* d_out, int out_size) {
    const float* x  = (const float*)d_in[0];
    const float* W1 = (const float*)d_in[1];
    const float* b1 = (const float*)d_in[2];
    const float* W2 = (const float*)d_in[3];
    const float* b2 = (const float*)d_in[4];
    float* out = (float*)d_out;

    sort_scatter_kernel<<<ROWS, 256>>>(x);
    gemm1_kernel<<<dim3(HDIM / 128, ROWS / 128), 256>>>(W1, b1);
    gemm2_kernel<<<dim3(FDIM / 128, ROWS / 128), 256>>>(W2, b2, out);
}

// round 3
// speedup vs baseline: 1.5105x; 1.5105x over previous
#include <cuda_runtime.h>
#include <cuda_fp16.h>
#include <cstdint>

#define ROWS 32768
#define FDIM 512
#define HDIM 2048

// ---------------- scratch (device globals; allocation-free) ----------------
__device__ float          g_xs32[(size_t)ROWS * FDIM];   // permuted input fp32 (skip add)
__device__ __half         g_xs16[(size_t)ROWS * FDIM];   // permuted input fp16 (GEMM1 A)
__device__ unsigned short g_inv [(size_t)ROWS * FDIM];   // inverse permutation
__device__ __half         g_h16 [(size_t)ROWS * HDIM];   // hidden activations fp16
__device__ __half         g_w1h [(size_t)HDIM * FDIM];   // W1 fp16
__device__ __half         g_w2h [(size_t)FDIM * HDIM];   // W2 fp16

// ---------------------------------------------------------------------------
// Weight conversion: fp32 -> fp16 (runs once per launch; tiny)
// ---------------------------------------------------------------------------
__global__ void cvt_weights(const float* __restrict__ W1, const float* __restrict__ W2) {
    const int QW = (HDIM * FDIM) / 4;
    int i = blockIdx.x * 256 + threadIdx.x;
    const float4* s;
    __half2* d;
    int j;
    if (i < QW) { s = (const float4*)W1; d = (__half2*)g_w1h; j = i; }
    else        { s = (const float4*)W2; d = (__half2*)g_w2h; j = i - QW; }
    float4 v = s[j];
    d[2 * j]     = __floats2half2_rn(v.x, v.y);
    d[2 * j + 1] = __floats2half2_rn(v.z, v.w);
}

// ---------------------------------------------------------------------------
// Sort: per-row stable bitonic, 4 keys/thread in registers, 128 threads/row,
// 2 rows per 256-thread block. Only strides 128/256 touch shared memory.
// key = ordered(float)<<32 | index.
// Epilogue reproduces the reference semantics EXACTLY:
//   srt[pos] = key payload at sorted pos; inv[srt[pos]] = pos;
//   xs[i] = x[inv[i]]  (gather of the RAW row by the inverse permutation)
// ---------------------------------------------------------------------------
__device__ __forceinline__ void cmpswap(unsigned long long& a, unsigned long long& b,
                                        bool asc) {
    bool sw = asc ? (a > b) : (a < b);
    if (sw) { unsigned long long t = a; a = b; b = t; }
}

__global__ __launch_bounds__(256)
void sort_kernel(const float* __restrict__ x) {
    __shared__ unsigned long long sk[2][FDIM];     // 8 KB
    __shared__ float              xsh[2][FDIM];    // 4 KB raw values
    __shared__ unsigned short     invsh[2][FDIM];  // 2 KB

    const int sub = threadIdx.x >> 7;
    const int t   = threadIdx.x & 127;
    const int row = blockIdx.x * 2 + sub;
    const int e0  = 4 * t;

    float4 v = reinterpret_cast<const float4*>(x + (size_t)row * FDIM)[t];
    unsigned long long k[4];
    {
        float vv[4] = {v.x, v.y, v.z, v.w};
#pragma unroll
        for (int s = 0; s < 4; s++) {
            xsh[sub][e0 + s] = vv[s];
            unsigned u = __float_as_uint(vv[s]);
            u = (u & 0x80000000u) ? ~u : (u | 0x80000000u);
            k[s] = ((unsigned long long)u << 32) | (unsigned)(e0 + s);
        }
    }

#pragma unroll
    for (int kk = 2; kk <= FDIM; kk <<= 1) {
#pragma unroll
        for (int j = kk >> 1; j >= 4; j >>= 1) {
            bool asc = ((e0 & kk) == 0);
            if (j <= 64) {
                int d = j >> 2;
                bool lower = ((t & d) == 0);
                bool takeMin = (lower == asc);
#pragma unroll
                for (int s = 0; s < 4; s++) {
                    unsigned long long o = __shfl_xor_sync(0xffffffffu, k[s], d);
                    bool mine = takeMin ? (k[s] <= o) : (k[s] >= o);
                    k[s] = mine ? k[s] : o;
                }
            } else {
#pragma unroll
                for (int s = 0; s < 4; s++) sk[sub][e0 + s] = k[s];
                __syncthreads();
#pragma unroll
                for (int s = 0; s < 4; s++) {
                    int e = e0 + s;
                    unsigned long long o = sk[sub][e ^ j];
                    bool lower = ((e & j) == 0);
                    bool takeMin = (lower == asc);
                    bool mine = takeMin ? (k[s] <= o) : (k[s] >= o);
                    k[s] = mine ? k[s] : o;
                }
                __syncthreads();
            }
        }
        if (kk >= 4) {
            bool asc = ((e0 & kk) == 0);
            cmpswap(k[0], k[2], asc);
            cmpswap(k[1], k[3], asc);
        }
        {
            bool a0 = (((e0)     & kk) == 0);
            bool a1 = (((e0 + 2) & kk) == 0);
            cmpswap(k[0], k[1], a0);
            cmpswap(k[2], k[3], a1);
        }
    }

    // inv[srt[pos]] = pos
#pragma unroll
    for (int s = 0; s < 4; s++)
        invsh[sub][(unsigned)(k[s] & 0xFFFFFFFFu)] = (unsigned short)(e0 + s);
    __syncthreads();

    // xs[i] = x[inv[i]] -- gather raw values by inverse permutation (ref semantics)
    ushort4 ivv;
    ivv.x = invsh[sub][e0];     ivv.y = invsh[sub][e0 + 1];
    ivv.z = invsh[sub][e0 + 2]; ivv.w = invsh[sub][e0 + 3];
    float xs0 = xsh[sub][ivv.x], xs1 = xsh[sub][ivv.y];
    float xs2 = xsh[sub][ivv.z], xs3 = xsh[sub][ivv.w];

    size_t base = (size_t)row * FDIM + e0;
    *reinterpret_cast<float4*>(&g_xs32[base]) = make_float4(xs0, xs1, xs2, xs3);
    __half2 hlo = __floats2half2_rn(xs0, xs1);
    __half2 hhi = __floats2half2_rn(xs2, xs3);
    uint2 hv = make_uint2(*reinterpret_cast<unsigned*>(&hlo),
                          *reinterpret_cast<unsigned*>(&hhi));
    *reinterpret_cast<uint2*>(&g_xs16[base]) = hv;
    *reinterpret_cast<ushort4*>(&g_inv[base]) = ivv;
}

// ---------------------------------------------------------------------------
// fp16 tensor-core GEMM: CTA tile 128x128, BK=64, 8 warps 2(M)x4(N),
// warp tile 64x32, mma.m16n8k16 f32 accum, ldmatrix fragment loads.
// A: [M][K] fp16 row-major, B: [N][K] fp16 row-major.
// ---------------------------------------------------------------------------
#define BK 64
#define LDS_STRIDE 72   // halves; 144B row stride: 16B-aligned

__device__ __forceinline__ void mma16816(float (&c)[4], const unsigned (&a)[4],
                                         const unsigned (&b)[2]) {
    asm volatile(
        "mma.sync.aligned.m16n8k16.row.col.f32.f16.f16.f32 "
        "{%0,%1,%2,%3}, {%4,%5,%6,%7}, {%8,%9}, {%0,%1,%2,%3};"
        : "+f"(c[0]), "+f"(c[1]), "+f"(c[2]), "+f"(c[3])
        : "r"(a[0]), "r"(a[1]), "r"(a[2]), "r"(a[3]), "r"(b[0]), "r"(b[1]));
}

template <int K>
__device__ __forceinline__ void gemm_body(
    const __half* __restrict__ A, const __half* __restrict__ B,
    float (&acc)[4][4][4], __half (*As)[LDS_STRIDE], __half (*Bs)[LDS_STRIDE]) {

    const int tid    = threadIdx.x;
    const int lane   = tid & 31;
    const int warp   = tid >> 5;
    const int warp_m = warp >> 2;
    const int warp_n = warp & 3;
    const int blockM = blockIdx.y * 128;
    const int blockN = blockIdx.x * 128;

    const int a_row = warp_m * 64 + (lane & 15);
    const int a_kof = (lane >> 4) << 3;
    const int b_row = warp_n * 32 + (lane & 7);
    const int b_kof = ((lane >> 3) & 1) << 3;

    for (int kt = 0; kt < K; kt += BK) {
#pragma unroll
        for (int i = 0; i < 4; i++) {
            int id = tid + i * 256;
            int r = id >> 3, c = (id & 7) * 8;
            *reinterpret_cast<uint4*>(&As[r][c]) =
                *reinterpret_cast<const uint4*>(&A[(size_t)(blockM + r) * K + kt + c]);
            *reinterpret_cast<uint4*>(&Bs[r][c]) =
                *reinterpret_cast<const uint4*>(&B[(size_t)(blockN + r) * K + kt + c]);
        }
        __syncthreads();

#pragma unroll
        for (int kk = 0; kk < BK; kk += 16) {
            unsigned a[4][4], b[4][2];
#pragma unroll
            for (int mf = 0; mf < 4; mf++) {
                unsigned addr = (unsigned)__cvta_generic_to_shared(
                    &As[a_row + mf * 16][kk + a_kof]);
                asm volatile(
                    "ldmatrix.sync.aligned.m8n8.x4.shared.b16 {%0,%1,%2,%3}, [%4];"
                    : "=r"(a[mf][0]), "=r"(a[mf][1]), "=r"(a[mf][2]), "=r"(a[mf][3])
                    : "r"(addr));
            }
#pragma unroll
            for (int nf = 0; nf < 4; nf++) {
                unsigned addr = (unsigned)__cvta_generic_to_shared(
                    &Bs[b_row + nf * 8][kk + b_kof]);
                asm volatile(
                    "ldmatrix.sync.aligned.m8n8.x2.shared.b16 {%0,%1}, [%2];"
                    : "=r"(b[nf][0]), "=r"(b[nf][1])
                    : "r"(addr));
            }
#pragma unroll
            for (int mf = 0; mf < 4; mf++)
#pragma unroll
                for (int nf = 0; nf < 4; nf++)
                    mma16816(acc[mf][nf], a[mf], b[nf]);
        }
        __syncthreads();
    }
}

// GEMM1: h = relu(xs @ W1^T + b1) -> fp16
__global__ __launch_bounds__(256, 2)
void gemm1_kernel(const float* __restrict__ b1) {
    __shared__ __half As[128][LDS_STRIDE];
    __shared__ __half Bs[128][LDS_STRIDE];
    float acc[4][4][4] = {};

    gemm_body<FDIM>(g_xs16, g_w1h, acc, As, Bs);

    const int tid  = threadIdx.x;
    const int lane = tid & 31;
    const int warp = tid >> 5;
    const int warp_m = warp >> 2, warp_n = warp & 3;
    const int blockM = blockIdx.y * 128;
    const int blockN = blockIdx.x * 128;

#pragma unroll
    for (int mf = 0; mf < 4; mf++)
#pragma unroll
        for (int nf = 0; nf < 4; nf++) {
            int row = blockM + warp_m * 64 + mf * 16 + (lane >> 2);
            int col = blockN + warp_n * 32 + nf * 8 + (lane & 3) * 2;
            float bb0 = b1[col], bb1 = b1[col + 1];
            __half2 h0 = __floats2half2_rn(fmaxf(acc[mf][nf][0] + bb0, 0.f),
                                           fmaxf(acc[mf][nf][1] + bb1, 0.f));
            __half2 h1 = __floats2half2_rn(fmaxf(acc[mf][nf][2] + bb0, 0.f),
                                           fmaxf(acc[mf][nf][3] + bb1, 0.f));
            *reinterpret_cast<__half2*>(&g_h16[(size_t)row * HDIM + col])       = h0;
            *reinterpret_cast<__half2*>(&g_h16[(size_t)(row + 8) * HDIM + col]) = h1;
        }
}

// GEMM2: y = h @ W2^T + b2 + xs; out[m][inv[n]] = y[m][n]
__global__ __launch_bounds__(256, 2)
void gemm2_kernel(const float* __restrict__ b2, float* __restrict__ out) {
    __shared__ __half As[128][LDS_STRIDE];
    __shared__ __half Bs[128][LDS_STRIDE];
    float acc[4][4][4] = {};

    gemm_body<HDIM>(g_h16, g_w2h, acc, As, Bs);

    const int tid  = threadIdx.x;
    const int lane = tid & 31;
    const int warp = tid >> 5;
    const int warp_m = warp >> 2, warp_n = warp & 3;
    const int blockM = blockIdx.y * 128;
    const int blockN = blockIdx.x * 128;

#pragma unroll
    for (int mf = 0; mf < 4; mf++)
#pragma unroll
        for (int nf = 0; nf < 4; nf++) {
            int row = blockM + warp_m * 64 + mf * 16 + (lane >> 2);
            int col = blockN + warp_n * 32 + nf * 8 + (lane & 3) * 2;
            float bb0 = b2[col], bb1 = b2[col + 1];
#pragma unroll
            for (int half = 0; half < 2; half++) {
                int r = row + half * 8;
                size_t base = (size_t)r * FDIM + col;
                float2 xsv = *reinterpret_cast<const float2*>(&g_xs32[base]);
                ushort2 pv = *reinterpret_cast<const ushort2*>(&g_inv[base]);
                float y0 = acc[mf][nf][half * 2 + 0] + bb0 + xsv.x;
                float y1 = acc[mf][nf][half * 2 + 1] + bb1 + xsv.y;
                out[(size_t)r * FDIM + pv.x] = y0;
                out[(size_t)r * FDIM + pv.y] = y1;
            }
        }
}

// ---------------------------------------------------------------------------
extern "C" void kernel_launch(void* const* d_in, const int* in_sizes, int n_in,
                              void* d_out, int out_size) {
    const float* x  = (const float*)d_in[0];
    const float* W1 = (const float*)d_in[1];
    const float* b1 = (const float*)d_in[2];
    const float* W2 = (const float*)d_in[3];
    const float* b2 = (const float*)d_in[4];
    float* out = (float*)d_out;

    cvt_weights<<<(2 * HDIM * FDIM / 4) / 256, 256>>>(W1, W2);
    sort_kernel<<<ROWS / 2, 256>>>(x);
    gemm1_kernel<<<dim3(HDIM / 128, ROWS / 128), 256>>>(b1);
    gemm2_kernel<<<dim3(FDIM / 128, ROWS / 128), 256>>>(b2, out);
}

// round 6
// speedup vs baseline: 1.5107x; 1.0002x over previous
#include <cuda_runtime.h>
#include <cuda_fp16.h>
#include <cstdint>

#define ROWS 32768
#define FDIM 512
#define HDIM 2048

// GEMM tiling: CTA 128x128, BK=32, 4-stage cp.async pipeline
#define BK 32
#define NSTAGE 4
#define LDSW 40                          // halves per smem row (80B, 16B-aligned)
#define STAGE_HALVES (128 * LDSW)        // 5120 halves = 10240 B per operand-stage
#define SMEM_TOTAL (2 * NSTAGE * STAGE_HALVES * 2)   // 81920 B

// ---------------- scratch (device globals; allocation-free) ----------------
__device__ float          g_xs32[(size_t)ROWS * FDIM];
__device__ __half         g_xs16[(size_t)ROWS * FDIM];
__device__ unsigned short g_inv [(size_t)ROWS * FDIM];
__device__ __half         g_h16 [(size_t)ROWS * HDIM];
__device__ __half         g_w1h [(size_t)HDIM * FDIM];
__device__ __half         g_w2h [(size_t)FDIM * HDIM];

// ---------------------------------------------------------------------------
__global__ void cvt_weights(const float* __restrict__ W1, const float* __restrict__ W2) {
    const int QW = (HDIM * FDIM) / 4;
    int i = blockIdx.x * 256 + threadIdx.x;
    const float4* s; __half2* d; int j;
    if (i < QW) { s = (const float4*)W1; d = (__half2*)g_w1h; j = i; }
    else        { s = (const float4*)W2; d = (__half2*)g_w2h; j = i - QW; }
    float4 v = s[j];
    d[2 * j]     = __floats2half2_rn(v.x, v.y);
    d[2 * j + 1] = __floats2half2_rn(v.z, v.w);
}

// ---------------------------------------------------------------------------
// Sort (register/shuffle bitonic; reference-exact xs = x gathered by inv)
// ---------------------------------------------------------------------------
__device__ __forceinline__ void cmpswap(unsigned long long& a, unsigned long long& b,
                                        bool asc) {
    bool sw = asc ? (a > b) : (a < b);
    if (sw) { unsigned long long t = a; a = b; b = t; }
}

__global__ __launch_bounds__(256)
void sort_kernel(const float* __restrict__ x) {
    __shared__ unsigned long long sk[2][FDIM];
    __shared__ float              xsh[2][FDIM];
    __shared__ unsigned short     invsh[2][FDIM];

    const int sub = threadIdx.x >> 7;
    const int t   = threadIdx.x & 127;
    const int row = blockIdx.x * 2 + sub;
    const int e0  = 4 * t;

    float4 v = reinterpret_cast<const float4*>(x + (size_t)row * FDIM)[t];
    unsigned long long k[4];
    {
        float vv[4] = {v.x, v.y, v.z, v.w};
#pragma unroll
        for (int s = 0; s < 4; s++) {
            xsh[sub][e0 + s] = vv[s];
            unsigned u = __float_as_uint(vv[s]);
            u = (u & 0x80000000u) ? ~u : (u | 0x80000000u);
            k[s] = ((unsigned long long)u << 32) | (unsigned)(e0 + s);
        }
    }

#pragma unroll
    for (int kk = 2; kk <= FDIM; kk <<= 1) {
#pragma unroll
        for (int j = kk >> 1; j >= 4; j >>= 1) {
            bool asc = ((e0 & kk) == 0);
            if (j <= 64) {
                int d = j >> 2;
                bool lower = ((t & d) == 0);
                bool takeMin = (lower == asc);
#pragma unroll
                for (int s = 0; s < 4; s++) {
                    unsigned long long o = __shfl_xor_sync(0xffffffffu, k[s], d);
                    bool mine = takeMin ? (k[s] <= o) : (k[s] >= o);
                    k[s] = mine ? k[s] : o;
                }
            } else {
#pragma unroll
                for (int s = 0; s < 4; s++) sk[sub][e0 + s] = k[s];
                __syncthreads();
#pragma unroll
                for (int s = 0; s < 4; s++) {
                    int e = e0 + s;
                    unsigned long long o = sk[sub][e ^ j];
                    bool lower = ((e & j) == 0);
                    bool takeMin = (lower == asc);
                    bool mine = takeMin ? (k[s] <= o) : (k[s] >= o);
                    k[s] = mine ? k[s] : o;
                }
                __syncthreads();
            }
        }
        if (kk >= 4) {
            bool asc = ((e0 & kk) == 0);
            cmpswap(k[0], k[2], asc);
            cmpswap(k[1], k[3], asc);
        }
        {
            bool a0 = (((e0)     & kk) == 0);
            bool a1 = (((e0 + 2) & kk) == 0);
            cmpswap(k[0], k[1], a0);
            cmpswap(k[2], k[3], a1);
        }
    }

#pragma unroll
    for (int s = 0; s < 4; s++)
        invsh[sub][(unsigned)(k[s] & 0xFFFFFFFFu)] = (unsigned short)(e0 + s);
    __syncthreads();

    ushort4 ivv;
    ivv.x = invsh[sub][e0];     ivv.y = invsh[sub][e0 + 1];
    ivv.z = invsh[sub][e0 + 2]; ivv.w = invsh[sub][e0 + 3];
    float xs0 = xsh[sub][ivv.x], xs1 = xsh[sub][ivv.y];
    float xs2 = xsh[sub][ivv.z], xs3 = xsh[sub][ivv.w];

    size_t base = (size_t)row * FDIM + e0;
    *reinterpret_cast<float4*>(&g_xs32[base]) = make_float4(xs0, xs1, xs2, xs3);
    __half2 hlo = __floats2half2_rn(xs0, xs1);
    __half2 hhi = __floats2half2_rn(xs2, xs3);
    uint2 hv = make_uint2(*reinterpret_cast<unsigned*>(&hlo),
                          *reinterpret_cast<unsigned*>(&hhi));
    *reinterpret_cast<uint2*>(&g_xs16[base]) = hv;
    *reinterpret_cast<ushort4*>(&g_inv[base]) = ivv;
}

// ---------------------------------------------------------------------------
// fp16 mma.sync GEMM, 4-stage cp.async pipeline.
// A: [M][K] f16 row-major, B: [N][K] f16 row-major. 8 warps 2(M)x4(N).
// ---------------------------------------------------------------------------
__device__ __forceinline__ void mma16816(float (&c)[4], const unsigned (&a)[4],
                                         const unsigned (&b)[2]) {
    asm volatile(
        "mma.sync.aligned.m16n8k16.row.col.f32.f16.f16.f32 "
        "{%0,%1,%2,%3}, {%4,%5,%6,%7}, {%8,%9}, {%0,%1,%2,%3};"
        : "+f"(c[0]), "+f"(c[1]), "+f"(c[2]), "+f"(c[3])
        : "r"(a[0]), "r"(a[1]), "r"(a[2]), "r"(a[3]), "r"(b[0]), "r"(b[1]));
}

__device__ __forceinline__ void cp16(uint32_t dst, const __half* src) {
    asm volatile("cp.async.cg.shared.global [%0], [%1], 16;"
                 :: "r"(dst), "l"(__cvta_generic_to_global(src)));
}
#define CP_COMMIT() asm volatile("cp.async.commit_group;" ::: "memory")
#define CP_WAIT2()  asm volatile("cp.async.wait_group 2;" ::: "memory")
#define CP_WAIT0()  asm volatile("cp.async.wait_group 0;" ::: "memory")

// load one 128x32-half chunk of A and B into stage.
// 2 threads per row; each thread copies 16 halves (2 x cp16) per operand.
// Coverage: 256 thr * 32 B = 8192 B per operand  ==  128 rows * 64 B. Exact.
template <int K>
__device__ __forceinline__ void load_chunk(uint32_t sA, uint32_t sB,
                                           const __half* __restrict__ A,
                                           const __half* __restrict__ B,
                                           int blockM, int blockN, int kt, int tid) {
    int r = tid >> 1;                    // 0..127
    int c = (tid & 1) * 16;              // 0 or 16 halves
    uint32_t so = (uint32_t)(r * LDSW + c) * 2;
    const __half* pa = A + (size_t)(blockM + r) * K + kt + c;
    const __half* pb = B + (size_t)(blockN + r) * K + kt + c;
    cp16(sA + so,      pa);
    cp16(sA + so + 16, pa + 8);
    cp16(sB + so,      pb);
    cp16(sB + so + 16, pb + 8);
}

template <int K>
__device__ __forceinline__ void gemm_body(
    const __half* __restrict__ A, const __half* __restrict__ B,
    float (&acc)[4][4][4], char* smem) {

    const uint32_t smem_base = (uint32_t)__cvta_generic_to_shared(smem);
    const int tid    = threadIdx.x;
    const int lane   = tid & 31;
    const int warp   = tid >> 5;
    const int warp_m = warp >> 2;
    const int warp_n = warp & 3;
    const int blockM = blockIdx.y * 128;
    const int blockN = blockIdx.x * 128;
    constexpr int NK = K / BK;

    const uint32_t A0 = smem_base;
    const uint32_t B0 = smem_base + NSTAGE * STAGE_HALVES * 2;

    const int a_row = warp_m * 64 + (lane & 15);
    const int a_kof = (lane >> 4) << 3;
    const int b_row = warp_n * 32 + (lane & 7);
    const int b_kof = ((lane >> 3) & 1) << 3;

    // prologue: chunks 0..NSTAGE-2
#pragma unroll
    for (int p = 0; p < NSTAGE - 1; p++) {
        load_chunk<K>(A0 + p * STAGE_HALVES * 2, B0 + p * STAGE_HALVES * 2,
                      A, B, blockM, blockN, p * BK, tid);
        CP_COMMIT();
    }

#pragma unroll 1
    for (int kc = 0; kc < NK; kc++) {
        const int stage = kc & (NSTAGE - 1);
        CP_WAIT2();             // group kc (carrying chunk kc) retired
        __syncthreads();

        // prefetch chunk kc+3 into the stage freed at iteration kc-1
        const int nf = kc + NSTAGE - 1;
        if (nf < NK) {
            const int ns = nf & (NSTAGE - 1);
            load_chunk<K>(A0 + ns * STAGE_HALVES * 2, B0 + ns * STAGE_HALVES * 2,
                          A, B, blockM, blockN, nf * BK, tid);
        }
        CP_COMMIT();

        const uint32_t sA = A0 + stage * STAGE_HALVES * 2;
        const uint32_t sB = B0 + stage * STAGE_HALVES * 2;
#pragma unroll
        for (int kk = 0; kk < BK; kk += 16) {
            unsigned a[4][4], b[4][2];
#pragma unroll
            for (int mf = 0; mf < 4; mf++) {
                uint32_t addr = sA + ((a_row + mf * 16) * LDSW + kk + a_kof) * 2;
                asm volatile(
                    "ldmatrix.sync.aligned.m8n8.x4.shared.b16 {%0,%1,%2,%3}, [%4];"
                    : "=r"(a[mf][0]), "=r"(a[mf][1]), "=r"(a[mf][2]), "=r"(a[mf][3])
                    : "r"(addr));
            }
#pragma unroll
            for (int nff = 0; nff < 4; nff++) {
                uint32_t addr = sB + ((b_row + nff * 8) * LDSW + kk + b_kof) * 2;
                asm volatile(
                    "ldmatrix.sync.aligned.m8n8.x2.shared.b16 {%0,%1}, [%2];"
                    : "=r"(b[nff][0]), "=r"(b[nff][1])
                    : "r"(addr));
            }
#pragma unroll
            for (int mf = 0; mf < 4; mf++)
#pragma unroll
                for (int nff = 0; nff < 4; nff++)
                    mma16816(acc[mf][nff], a[mf], b[nff]);
        }
    }
    CP_WAIT0();
}

// GEMM1: h = relu(xs @ W1^T + b1) -> fp16
__global__ __launch_bounds__(256, 2)
void gemm1_kernel(const float* __restrict__ b1) {
    extern __shared__ char smem[];
    float acc[4][4][4] = {};
    gemm_body<FDIM>(g_xs16, g_w1h, acc, smem);

    const int tid  = threadIdx.x;
    const int lane = tid & 31;
    const int warp = tid >> 5;
    const int warp_m = warp >> 2, warp_n = warp & 3;
    const int blockM = blockIdx.y * 128;
    const int blockN = blockIdx.x * 128;

#pragma unroll
    for (int mf = 0; mf < 4; mf++)
#pragma unroll
        for (int nf = 0; nf < 4; nf++) {
            int row = blockM + warp_m * 64 + mf * 16 + (lane >> 2);
            int col = blockN + warp_n * 32 + nf * 8 + (lane & 3) * 2;
            float bb0 = b1[col], bb1 = b1[col + 1];
            __half2 h0 = __floats2half2_rn(fmaxf(acc[mf][nf][0] + bb0, 0.f),
                                           fmaxf(acc[mf][nf][1] + bb1, 0.f));
            __half2 h1 = __floats2half2_rn(fmaxf(acc[mf][nf][2] + bb0, 0.f),
                                           fmaxf(acc[mf][nf][3] + bb1, 0.f));
            *reinterpret_cast<__half2*>(&g_h16[(size_t)row * HDIM + col])       = h0;
            *reinterpret_cast<__half2*>(&g_h16[(size_t)(row + 8) * HDIM + col]) = h1;
        }
}

// GEMM2: y = h @ W2^T + b2 + xs; out[m][inv[n]] = y[m][n]
__global__ __launch_bounds__(256, 2)
void gemm2_kernel(const float* __restrict__ b2, float* __restrict__ out) {
    extern __shared__ char smem[];
    float acc[4][4][4] = {};
    gemm_body<HDIM>(g_h16, g_w2h, acc, smem);

    const int tid  = threadIdx.x;
    const int lane = tid & 31;
    const int warp = tid >> 5;
    const int warp_m = warp >> 2, warp_n = warp & 3;
    const int blockM = blockIdx.y * 128;
    const int blockN = blockIdx.x * 128;

#pragma unroll
    for (int mf = 0; mf < 4; mf++)
#pragma unroll
        for (int nf = 0; nf < 4; nf++) {
            int row = blockM + warp_m * 64 + mf * 16 + (lane >> 2);
            int col = blockN + warp_n * 32 + nf * 8 + (lane & 3) * 2;
            float bb0 = b2[col], bb1 = b2[col + 1];
#pragma unroll
            for (int half = 0; half < 2; half++) {
                int r = row + half * 8;
                size_t base = (size_t)r * FDIM + col;
                float2 xsv = *reinterpret_cast<const float2*>(&g_xs32[base]);
                ushort2 pv = *reinterpret_cast<const ushort2*>(&g_inv[base]);
                float y0 = acc[mf][nf][half * 2 + 0] + bb0 + xsv.x;
                float y1 = acc[mf][nf][half * 2 + 1] + bb1 + xsv.y;
                out[(size_t)r * FDIM + pv.x] = y0;
                out[(size_t)r * FDIM + pv.y] = y1;
            }
        }
}

// ---------------------------------------------------------------------------
extern "C" void kernel_launch(void* const* d_in, const int* in_sizes, int n_in,
                              void* d_out, int out_size) {
    const float* x  = (const float*)d_in[0];
    const float* W1 = (const float*)d_in[1];
    const float* b1 = (const float*)d_in[2];
    const float* W2 = (const float*)d_in[3];
    const float* b2 = (const float*)d_in[4];
    float* out = (float*)d_out;

    cudaFuncSetAttribute(gemm1_kernel, cudaFuncAttributeMaxDynamicSharedMemorySize, SMEM_TOTAL);
    cudaFuncSetAttribute(gemm2_kernel, cudaFuncAttributeMaxDynamicSharedMemorySize, SMEM_TOTAL);

    cvt_weights<<<(2 * HDIM * FDIM / 4) / 256, 256>>>(W1, W2);
    sort_kernel<<<ROWS / 2, 256>>>(x);
    gemm1_kernel<<<dim3(HDIM / 128, ROWS / 128), 256, SMEM_TOTAL>>>(b1);
    gemm2_kernel<<<dim3(FDIM / 128, ROWS / 128), 256, SMEM_TOTAL>>>(b2, out);
}

// round 7
// speedup vs baseline: 1.5623x; 1.0341x over previous
#include <cuda_runtime.h>
#include <cuda_fp16.h>
#include <cstdint>

#define ROWS 32768
#define FDIM 512
#define HDIM 2048

// GEMM tiling: CTA 128x128, 512 threads (16 warps, 4Mx4N, warp tile 32x32),
// BK=32, 4-stage cp.async pipeline.
#define BK 32
#define NSTAGE 4
#define LDSW 40                          // halves per smem row (80B)
#define STAGE_HALVES (128 * LDSW)
#define SMEM_TOTAL (2 * NSTAGE * STAGE_HALVES * 2)   // 81920 B

// ---------------- scratch (device globals; allocation-free) ----------------
__device__ float          g_xs32[(size_t)ROWS * FDIM];
__device__ __half         g_xs16[(size_t)ROWS * FDIM];
__device__ unsigned short g_inv [(size_t)ROWS * FDIM];
__device__ __half         g_h16 [(size_t)ROWS * HDIM];
__device__ __half         g_w1h [(size_t)HDIM * FDIM];
__device__ __half         g_w2h [(size_t)FDIM * HDIM];

// ---------------------------------------------------------------------------
__global__ void cvt_weights(const float* __restrict__ W1, const float* __restrict__ W2) {
    const int QW = (HDIM * FDIM) / 4;
    int i = blockIdx.x * 256 + threadIdx.x;
    const float4* s; __half2* d; int j;
    if (i < QW) { s = (const float4*)W1; d = (__half2*)g_w1h; j = i; }
    else        { s = (const float4*)W2; d = (__half2*)g_w2h; j = i - QW; }
    float4 v = s[j];
    d[2 * j]     = __floats2half2_rn(v.x, v.y);
    d[2 * j + 1] = __floats2half2_rn(v.z, v.w);
}

// ---------------------------------------------------------------------------
// Sort (register/shuffle bitonic; reference-exact xs = x gathered by inv)
// ---------------------------------------------------------------------------
__device__ __forceinline__ void cmpswap(unsigned long long& a, unsigned long long& b,
                                        bool asc) {
    bool sw = asc ? (a > b) : (a < b);
    if (sw) { unsigned long long t = a; a = b; b = t; }
}

__global__ __launch_bounds__(256)
void sort_kernel(const float* __restrict__ x) {
    __shared__ unsigned long long sk[2][FDIM];
    __shared__ float              xsh[2][FDIM];
    __shared__ unsigned short     invsh[2][FDIM];

    const int sub = threadIdx.x >> 7;
    const int t   = threadIdx.x & 127;
    const int row = blockIdx.x * 2 + sub;
    const int e0  = 4 * t;

    float4 v = reinterpret_cast<const float4*>(x + (size_t)row * FDIM)[t];
    unsigned long long k[4];
    {
        float vv[4] = {v.x, v.y, v.z, v.w};
#pragma unroll
        for (int s = 0; s < 4; s++) {
            xsh[sub][e0 + s] = vv[s];
            unsigned u = __float_as_uint(vv[s]);
            u = (u & 0x80000000u) ? ~u : (u | 0x80000000u);
            k[s] = ((unsigned long long)u << 32) | (unsigned)(e0 + s);
        }
    }

#pragma unroll
    for (int kk = 2; kk <= FDIM; kk <<= 1) {
#pragma unroll
        for (int j = kk >> 1; j >= 4; j >>= 1) {
            bool asc = ((e0 & kk) == 0);
            if (j <= 64) {
                int d = j >> 2;
                bool lower = ((t & d) == 0);
                bool takeMin = (lower == asc);
#pragma unroll
                for (int s = 0; s < 4; s++) {
                    unsigned long long o = __shfl_xor_sync(0xffffffffu, k[s], d);
                    bool mine = takeMin ? (k[s] <= o) : (k[s] >= o);
                    k[s] = mine ? k[s] : o;
                }
            } else {
#pragma unroll
                for (int s = 0; s < 4; s++) sk[sub][e0 + s] = k[s];
                __syncthreads();
#pragma unroll
                for (int s = 0; s < 4; s++) {
                    int e = e0 + s;
                    unsigned long long o = sk[sub][e ^ j];
                    bool lower = ((e & j) == 0);
                    bool takeMin = (lower == asc);
                    bool mine = takeMin ? (k[s] <= o) : (k[s] >= o);
                    k[s] = mine ? k[s] : o;
                }
                __syncthreads();
            }
        }
        if (kk >= 4) {
            bool asc = ((e0 & kk) == 0);
            cmpswap(k[0], k[2], asc);
            cmpswap(k[1], k[3], asc);
        }
        {
            bool a0 = (((e0)     & kk) == 0);
            bool a1 = (((e0 + 2) & kk) == 0);
            cmpswap(k[0], k[1], a0);
            cmpswap(k[2], k[3], a1);
        }
    }

#pragma unroll
    for (int s = 0; s < 4; s++)
        invsh[sub][(unsigned)(k[s] & 0xFFFFFFFFu)] = (unsigned short)(e0 + s);
    __syncthreads();

    ushort4 ivv;
    ivv.x = invsh[sub][e0];     ivv.y = invsh[sub][e0 + 1];
    ivv.z = invsh[sub][e0 + 2]; ivv.w = invsh[sub][e0 + 3];
    float xs0 = xsh[sub][ivv.x], xs1 = xsh[sub][ivv.y];
    float xs2 = xsh[sub][ivv.z], xs3 = xsh[sub][ivv.w];

    size_t base = (size_t)row * FDIM + e0;
    *reinterpret_cast<float4*>(&g_xs32[base]) = make_float4(xs0, xs1, xs2, xs3);
    __half2 hlo = __floats2half2_rn(xs0, xs1);
    __half2 hhi = __floats2half2_rn(xs2, xs3);
    uint2 hv = make_uint2(*reinterpret_cast<unsigned*>(&hlo),
                          *reinterpret_cast<unsigned*>(&hhi));
    *reinterpret_cast<uint2*>(&g_xs16[base]) = hv;
    *reinterpret_cast<ushort4*>(&g_inv[base]) = ivv;
}

// ---------------------------------------------------------------------------
// fp16 mma.sync GEMM, 512 threads, warp tile 32x32, 4-stage cp.async pipe.
// A: [M][K] f16 row-major, B: [N][K] f16 row-major.
// ---------------------------------------------------------------------------
__device__ __forceinline__ void mma16816(float (&c)[4], unsigned a0, unsigned a1,
                                         unsigned a2, unsigned a3,
                                         unsigned b0, unsigned b1) {
    asm volatile(
        "mma.sync.aligned.m16n8k16.row.col.f32.f16.f16.f32 "
        "{%0,%1,%2,%3}, {%4,%5,%6,%7}, {%8,%9}, {%0,%1,%2,%3};"
        : "+f"(c[0]), "+f"(c[1]), "+f"(c[2]), "+f"(c[3])
        : "r"(a0), "r"(a1), "r"(a2), "r"(a3), "r"(b0), "r"(b1));
}

__device__ __forceinline__ void cp16(uint32_t dst, const __half* src) {
    asm volatile("cp.async.cg.shared.global [%0], [%1], 16;"
                 :: "r"(dst), "l"(__cvta_generic_to_global(src)));
}
#define CP_COMMIT() asm volatile("cp.async.commit_group;" ::: "memory")
#define CP_WAIT2()  asm volatile("cp.async.wait_group 2;" ::: "memory")
#define CP_WAIT0()  asm volatile("cp.async.wait_group 0;" ::: "memory")

// load one 128x32-half chunk of A and B. 512 threads: 4/row, 16B each.
template <int K>
__device__ __forceinline__ void load_chunk(uint32_t sA, uint32_t sB,
                                           const __half* __restrict__ A,
                                           const __half* __restrict__ B,
                                           int blockM, int blockN, int kt, int tid) {
    int r = tid >> 2;                    // 0..127
    int c = (tid & 3) * 8;               // 0,8,16,24 halves
    uint32_t so = (uint32_t)(r * LDSW + c) * 2;
    cp16(sA + so, A + (size_t)(blockM + r) * K + kt + c);
    cp16(sB + so, B + (size_t)(blockN + r) * K + kt + c);
}

template <int K>
__device__ __forceinline__ void gemm_body(
    const __half* __restrict__ A, const __half* __restrict__ B,
    float (&acc)[2][4][4], char* smem) {

    const uint32_t smem_base = (uint32_t)__cvta_generic_to_shared(smem);
    const int tid    = threadIdx.x;
    const int lane   = tid & 31;
    const int warp   = tid >> 5;          // 0..15
    const int warp_m = warp >> 2;         // 0..3
    const int warp_n = warp & 3;          // 0..3
    const int blockM = blockIdx.y * 128;
    const int blockN = blockIdx.x * 128;
    constexpr int NK = K / BK;

    const uint32_t A0 = smem_base;
    const uint32_t B0 = smem_base + NSTAGE * STAGE_HALVES * 2;

    // ldmatrix.x4 source rows/cols (same pattern for A and B)
    const int a_row = warp_m * 32 + (lane & 15);
    const int b_row = warp_n * 32 + (lane & 15);
    const int kof   = (lane >> 4) << 3;

    // prologue
#pragma unroll
    for (int p = 0; p < NSTAGE - 1; p++) {
        load_chunk<K>(A0 + p * STAGE_HALVES * 2, B0 + p * STAGE_HALVES * 2,
                      A, B, blockM, blockN, p * BK, tid);
        CP_COMMIT();
    }

#pragma unroll 1
    for (int kc = 0; kc < NK; kc++) {
        const int stage = kc & (NSTAGE - 1);
        CP_WAIT2();
        __syncthreads();

        const int nf = kc + NSTAGE - 1;
        if (nf < NK) {
            const int ns = nf & (NSTAGE - 1);
            load_chunk<K>(A0 + ns * STAGE_HALVES * 2, B0 + ns * STAGE_HALVES * 2,
                          A, B, blockM, blockN, nf * BK, tid);
        }
        CP_COMMIT();

        const uint32_t sA = A0 + stage * STAGE_HALVES * 2;
        const uint32_t sB = B0 + stage * STAGE_HALVES * 2;
#pragma unroll
        for (int kk = 0; kk < BK; kk += 16) {
            unsigned a[2][4], b[2][4];
#pragma unroll
            for (int mf = 0; mf < 2; mf++) {
                uint32_t addr = sA + ((a_row + mf * 16) * LDSW + kk + kof) * 2;
                asm volatile(
                    "ldmatrix.sync.aligned.m8n8.x4.shared.b16 {%0,%1,%2,%3}, [%4];"
                    : "=r"(a[mf][0]), "=r"(a[mf][1]), "=r"(a[mf][2]), "=r"(a[mf][3])
                    : "r"(addr));
            }
#pragma unroll
            for (int g = 0; g < 2; g++) {
                uint32_t addr = sB + ((b_row + g * 16) * LDSW + kk + kof) * 2;
                asm volatile(
                    "ldmatrix.sync.aligned.m8n8.x4.shared.b16 {%0,%1,%2,%3}, [%4];"
                    : "=r"(b[g][0]), "=r"(b[g][1]), "=r"(b[g][2]), "=r"(b[g][3])
                    : "r"(addr));
            }
            // n-frag nn (8 cols): regs {b[nn>>1][nn&1], b[nn>>1][(nn&1)+2]}
#pragma unroll
            for (int mf = 0; mf < 2; mf++)
#pragma unroll
                for (int nn = 0; nn < 4; nn++)
                    mma16816(acc[mf][nn], a[mf][0], a[mf][1], a[mf][2], a[mf][3],
                             b[nn >> 1][nn & 1], b[nn >> 1][(nn & 1) + 2]);
        }
    }
    CP_WAIT0();
}

// GEMM1: h = relu(xs @ W1^T + b1) -> fp16
__global__ __launch_bounds__(512, 2)
void gemm1_kernel(const float* __restrict__ b1) {
    extern __shared__ char smem[];
    float acc[2][4][4] = {};
    gemm_body<FDIM>(g_xs16, g_w1h, acc, smem);

    const int tid  = threadIdx.x;
    const int lane = tid & 31;
    const int warp = tid >> 5;
    const int warp_m = warp >> 2, warp_n = warp & 3;
    const int blockM = blockIdx.y * 128;
    const int blockN = blockIdx.x * 128;

#pragma unroll
    for (int mf = 0; mf < 2; mf++)
#pragma unroll
        for (int nn = 0; nn < 4; nn++) {
            int row = blockM + warp_m * 32 + mf * 16 + (lane >> 2);
            int col = blockN + warp_n * 32 + nn * 8 + (lane & 3) * 2;
            float bb0 = b1[col], bb1 = b1[col + 1];
            __half2 h0 = __floats2half2_rn(fmaxf(acc[mf][nn][0] + bb0, 0.f),
                                           fmaxf(acc[mf][nn][1] + bb1, 0.f));
            __half2 h1 = __floats2half2_rn(fmaxf(acc[mf][nn][2] + bb0, 0.f),
                                           fmaxf(acc[mf][nn][3] + bb1, 0.f));
            *reinterpret_cast<__half2*>(&g_h16[(size_t)row * HDIM + col])       = h0;
            *reinterpret_cast<__half2*>(&g_h16[(size_t)(row + 8) * HDIM + col]) = h1;
        }
}

// GEMM2: y = h @ W2^T + b2 + xs; out[m][inv[n]] = y[m][n]
__global__ __launch_bounds__(512, 2)
void gemm2_kernel(const float* __restrict__ b2, float* __restrict__ out) {
    extern __shared__ char smem[];
    float acc[2][4][4] = {};
    gemm_body<HDIM>(g_h16, g_w2h, acc, smem);

    const int tid  = threadIdx.x;
    const int lane = tid & 31;
    const int warp = tid >> 5;
    const int warp_m = warp >> 2, warp_n = warp & 3;
    const int blockM = blockIdx.y * 128;
    const int blockN = blockIdx.x * 128;

#pragma unroll
    for (int mf = 0; mf < 2; mf++)
#pragma unroll
        for (int nn = 0; nn < 4; nn++) {
            int row = blockM + warp_m * 32 + mf * 16 + (lane >> 2);
            int col = blockN + warp_n * 32 + nn * 8 + (lane & 3) * 2;
            float bb0 = b2[col], bb1 = b2[col + 1];
#pragma unroll
            for (int half = 0; half < 2; half++) {
                int r = row + half * 8;
                size_t base = (size_t)r * FDIM + col;
                float2 xsv = *reinterpret_cast<const float2*>(&g_xs32[base]);
                ushort2 pv = *reinterpret_cast<const ushort2*>(&g_inv[base]);
                float y0 = acc[mf][nn][half * 2 + 0] + bb0 + xsv.x;
                float y1 = acc[mf][nn][half * 2 + 1] + bb1 + xsv.y;
                out[(size_t)r * FDIM + pv.x] = y0;
                out[(size_t)r * FDIM + pv.y] = y1;
            }
        }
}

// ---------------------------------------------------------------------------
extern "C" void kernel_launch(void* const* d_in, const int* in_sizes, int n_in,
                              void* d_out, int out_size) {
    const float* x  = (const float*)d_in[0];
    const float* W1 = (const float*)d_in[1];
    const float* b1 = (const float*)d_in[2];
    const float* W2 = (const float*)d_in[3];
    const float* b2 = (const float*)d_in[4];
    float* out = (float*)d_out;

    cudaFuncSetAttribute(gemm1_kernel, cudaFuncAttributeMaxDynamicSharedMemorySize, SMEM_TOTAL);
    cudaFuncSetAttribute(gemm2_kernel, cudaFuncAttributeMaxDynamicSharedMemorySize, SMEM_TOTAL);

    cvt_weights<<<(2 * HDIM * FDIM / 4) / 256, 256>>>(W1, W2);
    sort_kernel<<<ROWS / 2, 256>>>(x);
    gemm1_kernel<<<dim3(HDIM / 128, ROWS / 128), 512, SMEM_TOTAL>>>(b1);
    gemm2_kernel<<<dim3(FDIM / 128, ROWS / 128), 512, SMEM_TOTAL>>>(b2, out);
}